// round 3
// baseline (speedup 1.0000x reference)
#include <cuda_runtime.h>
#include <math.h>

#define NTOK 16384
#define DDIM 2048
#define NEXP 64
#define CAP  256

// ---------------- scratch (static device globals: allocation-free) ----------------
__device__ __align__(16) float g_aff[NEXP * NTOK];      // affinity [e][n], 4 MB
__device__ int   g_counts[NTOK];
__device__ int   g_sel_idx[NEXP * CAP];
__device__ float g_sel_prob[NEXP * CAP];

// ---------------- GEMM: aff[e][n] = sum_d tok[n][d] * wsel[e][d] ----------------
// Block tile: 64 tokens x 64 experts. 256 threads, thread tile 4 tok x 4 exp.
// Packed fp32x2 FMAs (2 FMAs/instr) keep full fp32 accuracy at 2x FFMA rate.
#define TM   64
#define DK   32
#define TPAD 68

__device__ __forceinline__ void fma2(unsigned long long &d, unsigned long long a,
                                     unsigned long long b) {
    asm("fma.rn.f32x2 %0, %1, %2, %0;" : "+l"(d) : "l"(a), "l"(b));
}
__device__ __forceinline__ unsigned long long bcast2(float w) {
    unsigned long long r; unsigned u = __float_as_uint(w);
    asm("mov.b64 %0, {%1, %1};" : "=l"(r) : "r"(u));
    return r;
}

__global__ __launch_bounds__(256, 2) void gemm_kernel(const float* __restrict__ tok,
                                                      const float* __restrict__ wsel) {
    __shared__ __align__(16) float sT[DK][TPAD];   // [k][token], padded
    __shared__ __align__(16) float sW[DK][TPAD];   // [k][expert], padded

    const int tid = threadIdx.x;
    const int n0  = blockIdx.x * TM;
    const int tx  = tid & 15;    // token group: tokens tx*4 .. tx*4+3
    const int ty  = tid >> 4;    // expert group: experts ty*4 .. ty*4+3

    unsigned long long acc[4][2];
    #pragma unroll
    for (int e = 0; e < 4; e++) { acc[e][0] = 0ull; acc[e][1] = 0ull; }

    // staging-index precompute: 512 float4 per tile for tokens (64 rows x 8 quads)
    int tTok[2], tQ[2], wE[2], wQ[2];
    #pragma unroll
    for (int j = 0; j < 2; j++) {
        int f = tid + j * 256;
        tTok[j] = f >> 3; tQ[j] = f & 7;
        wE[j]   = f >> 3; wQ[j] = f & 7;
    }

    float4 rT[2], rW[2];
    // prefetch chunk 0
    #pragma unroll
    for (int j = 0; j < 2; j++) {
        rT[j] = *(const float4*)&tok[(size_t)(n0 + tTok[j]) * DDIM + tQ[j] * 4];
        rW[j] = *(const float4*)&wsel[(size_t)wE[j] * DDIM + wQ[j] * 4];
    }

    const int NC = DDIM / DK;   // 64 chunks
    for (int c = 0; c < NC; c++) {
        // stage regs -> smem (transposed to [k][row] for vector LDS)
        #pragma unroll
        for (int j = 0; j < 2; j++) {
            int q4 = tQ[j] * 4, tkn = tTok[j];
            sT[q4 + 0][tkn] = rT[j].x; sT[q4 + 1][tkn] = rT[j].y;
            sT[q4 + 2][tkn] = rT[j].z; sT[q4 + 3][tkn] = rT[j].w;
            int p4 = wQ[j] * 4, ee = wE[j];
            sW[p4 + 0][ee] = rW[j].x; sW[p4 + 1][ee] = rW[j].y;
            sW[p4 + 2][ee] = rW[j].z; sW[p4 + 3][ee] = rW[j].w;
        }
        __syncthreads();

        // prefetch next chunk (consumed after compute -> latency hidden)
        if (c + 1 < NC) {
            int dbase = (c + 1) * DK;
            #pragma unroll
            for (int j = 0; j < 2; j++) {
                rT[j] = *(const float4*)&tok[(size_t)(n0 + tTok[j]) * DDIM + dbase + tQ[j] * 4];
                rW[j] = *(const float4*)&wsel[(size_t)wE[j] * DDIM + dbase + wQ[j] * 4];
            }
        }

        #pragma unroll
        for (int k = 0; k < DK; k++) {
            ulonglong2 A = *(const ulonglong2*)&sT[k][tx * 4];   // 4 tokens as 2 f32x2
            float4 w = *(const float4*)&sW[k][ty * 4];
            unsigned long long b0 = bcast2(w.x), b1 = bcast2(w.y);
            unsigned long long b2 = bcast2(w.z), b3 = bcast2(w.w);
            fma2(acc[0][0], A.x, b0); fma2(acc[0][1], A.y, b0);
            fma2(acc[1][0], A.x, b1); fma2(acc[1][1], A.y, b1);
            fma2(acc[2][0], A.x, b2); fma2(acc[2][1], A.y, b2);
            fma2(acc[3][0], A.x, b3); fma2(acc[3][1], A.y, b3);
        }
        __syncthreads();
    }

    // epilogue: packed low float = lower token index (little-endian) -> direct 8B store
    #pragma unroll
    for (int e = 0; e < 4; e++) {
        size_t base = (size_t)(ty * 4 + e) * NTOK + n0 + tx * 4;
        *(unsigned long long*)&g_aff[base]     = acc[e][0];
        *(unsigned long long*)&g_aff[base + 2] = acc[e][1];
    }
}

// ---------------- per-expert top-256 + softmax (exact fp32 radix select) ----------
// Monotonic key: ascending uint order == ascending float order.
__device__ __forceinline__ unsigned f2key(float v) {
    unsigned u = __float_as_uint(v);
    return (u & 0x80000000u) ? ~u : (u | 0x80000000u);
}

__global__ __launch_bounds__(256) void topk_kernel() {
    const int e   = blockIdx.x;
    const int tid = threadIdx.x;
    const float* __restrict__ row = g_aff + (size_t)e * NTOK;

    __shared__ unsigned hist[2048];
    __shared__ unsigned chunksum[257];
    __shared__ unsigned sh_prefix, sh_kneed, sh_bin, sh_above;
    __shared__ int   s_idx[CAP];
    __shared__ float s_val[CAP];
    __shared__ int   tie_buf[64];
    __shared__ int   sel_n, tie_n;
    __shared__ float red[10];

    if (tid == 0) { sh_prefix = 0u; sh_kneed = CAP; sel_n = 0; tie_n = 0; }

    const int      shifts[3]   = {21, 10, 0};
    const unsigned binmask[3]  = {2047u, 2047u, 1023u};
    const unsigned donemask[3] = {0u, 0xFFE00000u, 0xFFFFFC00u};

    for (int r = 0; r < 3; r++) {
        for (int b = tid; b < 2048; b += 256) hist[b] = 0u;
        __syncthreads();                 // also publishes sh_prefix/sh_kneed updates

        const unsigned pfx = sh_prefix;
        const unsigned dm  = donemask[r];
        const int      sh  = shifts[r];
        const unsigned bm  = binmask[r];

        #pragma unroll 4
        for (int j = 0; j < NTOK / 256; j++) {
            unsigned key = f2key(row[tid + j * 256]);
            if ((key & dm) == pfx) atomicAdd(&hist[(key >> sh) & bm], 1u);
        }
        __syncthreads();

        // block suffix scan over 256 chunks of 8 bins
        unsigned S = 0;
        #pragma unroll
        for (int q = 0; q < 8; q++) S += hist[tid * 8 + q];
        chunksum[tid] = S;
        __syncthreads();
        for (int off = 1; off < 256; off <<= 1) {
            unsigned v = (tid + off < 256) ? chunksum[tid + off] : 0u;
            __syncthreads();
            chunksum[tid] += v;
            __syncthreads();
        }
        // find pivot bin (from the top) s.t. cnt(key-bin > b) < kneed <= cnt(>= b)
        const unsigned kneed = sh_kneed;
        unsigned above = (tid < 255) ? chunksum[tid + 1] : 0u;
        for (int b = tid * 8 + 7; b >= tid * 8; b--) {
            unsigned h = hist[b];
            if (kneed > above && kneed <= above + h) { sh_bin = (unsigned)b; sh_above = above; }
            above += h;
        }
        __syncthreads();
        if (tid == 0) {
            sh_prefix |= (sh_bin << shifts[r]);
            sh_kneed  -= sh_above;
        }
    }
    __syncthreads();
    const unsigned T    = sh_prefix;  // exact 32-bit key of threshold value
    const unsigned krem = sh_kneed;   // #ties at T to include (lowest indices first)

    // collect: key > T definitely in; key == T are tie candidates
    #pragma unroll 4
    for (int j = 0; j < NTOK / 256; j++) {
        int i = tid + j * 256;
        float v = row[i];
        unsigned key = f2key(v);
        if (key > T) {
            int p = atomicAdd(&sel_n, 1);
            s_idx[p] = i; s_val[p] = v;
        } else if (key == T) {
            int p = atomicAdd(&tie_n, 1);
            if (p < 64) tie_buf[p] = i;
        }
    }
    __syncthreads();
    int tn = tie_n; if (tn > 64) tn = 64;
    if (tid < tn) {
        int my = tie_buf[tid], rank = 0;
        for (int j = 0; j < tn; j++) rank += (tie_buf[j] < my);
        if (rank < (int)krem) {
            int p = atomicAdd(&sel_n, 1);
            s_idx[p] = my; s_val[p] = row[my];
        }
    }
    __syncthreads();

    // softmax over the 256 selected scores (thread t owns entry t)
    float v = s_val[tid];
    float m = v;
    #pragma unroll
    for (int o = 16; o; o >>= 1) m = fmaxf(m, __shfl_xor_sync(0xffffffffu, m, o));
    if ((tid & 31) == 0) red[tid >> 5] = m;
    __syncthreads();
    if (tid == 0) {
        float t = red[0];
        #pragma unroll
        for (int i = 1; i < 8; i++) t = fmaxf(t, red[i]);
        red[8] = t;
    }
    __syncthreads();
    float ex = expf(v - red[8]);
    float s = ex;
    #pragma unroll
    for (int o = 16; o; o >>= 1) s += __shfl_xor_sync(0xffffffffu, s, o);
    if ((tid & 31) == 0) red[tid >> 5] = s;
    __syncthreads();
    if (tid == 0) {
        float t = 0.f;
        #pragma unroll
        for (int i = 0; i < 8; i++) t += red[i];
        red[9] = t;
    }
    __syncthreads();
    float prob = ex / red[9];

    g_sel_idx[e * CAP + tid]  = s_idx[tid];
    g_sel_prob[e * CAP + tid] = prob;
    atomicAdd(&g_counts[s_idx[tid]], 1);
}

// ---------------- output fill (zeros + capacity tail) + counts reset ----------------
__global__ void fill_kernel(float* __restrict__ out, long long out_size) {
    long long g = (long long)blockIdx.x * blockDim.x + threadIdx.x;
    long long stride = (long long)gridDim.x * blockDim.x;
    const long long NE2 = 2LL * NTOK * NEXP;

    float4 z4 = make_float4(0.f, 0.f, 0.f, 0.f);
    float4* o4 = (float4*)out;
    long long n4 = NE2 >> 2;               // NE2 divisible by 4
    long long lim4 = (out_size >> 2) < n4 ? (out_size >> 2) : n4;
    for (long long i = g; i < lim4; i += stride) o4[i] = z4;
    for (long long i = NE2 + g; i < out_size; i += stride) out[i] = (float)CAP;

    for (long long i = g; i < NTOK; i += stride) g_counts[i] = 0;
}

// ---------------- scatter: weights = prob/count, assignments = 1 ----------------
__global__ void scatter_kernel(float* __restrict__ out) {
    int idx = blockIdx.x * blockDim.x + threadIdx.x;   // 0 .. E*CAP-1
    int e = idx >> 8;
    int n = g_sel_idx[idx];
    float p = g_sel_prob[idx];
    int c = g_counts[n];                                // >= 1 for any selected token
    out[(size_t)n * NEXP + e] = p / (float)c;
    out[(size_t)NTOK * NEXP + (size_t)n * NEXP + e] = 1.0f;
}

// ---------------- launch ----------------
extern "C" void kernel_launch(void* const* d_in, const int* in_sizes, int n_in,
                              void* d_out, int out_size) {
    (void)in_sizes; (void)n_in;
    const float* hs = (const float*)d_in[0];   // hidden_states [4,4096,2048] fp32
    const float* ws = (const float*)d_in[1];   // w_sel [64,2048] fp32
    float* out = (float*)d_out;

    fill_kernel<<<2048, 256>>>(out, (long long)out_size);
    gemm_kernel<<<NTOK / TM, 256>>>(hs, ws);
    topk_kernel<<<NEXP, 256>>>();
    scatter_kernel<<<NEXP * CAP / 256, 256>>>(out);
}

// round 4
// speedup vs baseline: 1.0571x; 1.0571x over previous
#include <cuda_runtime.h>
#include <math.h>

#define NTOK 16384
#define DDIM 2048
#define NEXP 64
#define CAP  256

// GEMM tiling
#define BT    128          // tokens per block
#define BE    64           // experts per block (= NEXP)
#define DK    16           // k-chunk
#define STPAD 132          // sT row stride (floats), 16B-aligned rows
#define SWPAD 68           // sW row stride (floats)

// ---------------- scratch (static device globals: allocation-free) ----------------
__device__ __align__(16) float g_aff[NEXP * NTOK];      // affinity [e][n], 4 MB
__device__ int   g_counts[NTOK];
__device__ int   g_sel_idx[NEXP * CAP];
__device__ float g_sel_prob[NEXP * CAP];

// ---------------- packed fp32x2 helpers (2 fp32 FMAs per instruction) ----------------
__device__ __forceinline__ void fma2(unsigned long long &d, unsigned long long a,
                                     unsigned long long b) {
    asm("fma.rn.f32x2 %0, %1, %2, %0;" : "+l"(d) : "l"(a), "l"(b));
}
__device__ __forceinline__ unsigned long long bcast2(float w) {
    unsigned long long r; unsigned u = __float_as_uint(w);
    asm("mov.b64 %0, {%1, %1};" : "=l"(r) : "r"(u));
    return r;
}

// ---------------- GEMM: aff[e][n] = sum_d tok[n][d] * wsel[e][d] ----------------
// Block: 128 tokens x 64 experts, 128 threads, thread tile 8 tok x 8 exp.
// LDS-return traffic: 1 B/FMA (vs 2 B/FMA in the 4x4 version).
__global__ __launch_bounds__(128, 1) void gemm_kernel(const float* __restrict__ tok,
                                                      const float* __restrict__ wsel) {
    __shared__ __align__(16) float sT[DK][STPAD];   // [k][token]
    __shared__ __align__(16) float sW[DK][SWPAD];   // [k][expert]

    const int tid = threadIdx.x;
    const int n0  = blockIdx.x * BT;
    const int tx  = tid & 15;    // token groups: tx*4..+3 and 64+tx*4..+3
    const int ty  = tid >> 4;    // expert groups: ty*4..+3 and 32+ty*4..+3

    unsigned long long acc[8][4];
    #pragma unroll
    for (int e = 0; e < 8; e++)
        #pragma unroll
        for (int p = 0; p < 4; p++) acc[e][p] = 0ull;

    // --- staging assignment ---
    // tokens: idx = tid + j*128 (j=0..3): tok = tid>>2 + 32j, q = tid&3 (fixed).
    //   -> 4 lanes per 64B row-chunk: 8 lines per LDG instruction, sectors fully used.
    // experts: idx = tid + j*128 (j=0..1): e = tid&63, q = (tid>>6) + 2j.
    const int tTok = tid >> 2;
    const int tQ   = tid & 3;
    const int wEe  = tid & 63;
    const int wQ0  = tid >> 6;

    float4 rT[4], rW[2];
    // prefetch chunk 0
    #pragma unroll
    for (int j = 0; j < 4; j++)
        rT[j] = *(const float4*)&tok[(size_t)(n0 + tTok + 32 * j) * DDIM + tQ * 4];
    #pragma unroll
    for (int j = 0; j < 2; j++)
        rW[j] = *(const float4*)&wsel[(size_t)wEe * DDIM + (wQ0 + 2 * j) * 4];

    const int NC = DDIM / DK;   // 128 chunks
    for (int c = 0; c < NC; c++) {
        // stage regs -> smem (transposed to [k][row])
        #pragma unroll
        for (int j = 0; j < 4; j++) {
            int r = tTok + 32 * j, q4 = tQ * 4;
            sT[q4 + 0][r] = rT[j].x; sT[q4 + 1][r] = rT[j].y;
            sT[q4 + 2][r] = rT[j].z; sT[q4 + 3][r] = rT[j].w;
        }
        #pragma unroll
        for (int j = 0; j < 2; j++) {
            int q4 = (wQ0 + 2 * j) * 4;
            sW[q4 + 0][wEe] = rW[j].x; sW[q4 + 1][wEe] = rW[j].y;
            sW[q4 + 2][wEe] = rW[j].z; sW[q4 + 3][wEe] = rW[j].w;
        }
        __syncthreads();

        // prefetch next chunk into regs (consumed after compute)
        if (c + 1 < NC) {
            int dbase = (c + 1) * DK;
            #pragma unroll
            for (int j = 0; j < 4; j++)
                rT[j] = *(const float4*)&tok[(size_t)(n0 + tTok + 32 * j) * DDIM + dbase + tQ * 4];
            #pragma unroll
            for (int j = 0; j < 2; j++)
                rW[j] = *(const float4*)&wsel[(size_t)wEe * DDIM + dbase + (wQ0 + 2 * j) * 4];
        }

        #pragma unroll
        for (int k = 0; k < DK; k++) {
            ulonglong2 A0 = *(const ulonglong2*)&sT[k][tx * 4];        // tokens tx*4..+3
            ulonglong2 A1 = *(const ulonglong2*)&sT[k][64 + tx * 4];   // tokens 64+tx*4..+3
            float4 w0 = *(const float4*)&sW[k][ty * 4];
            float4 w1 = *(const float4*)&sW[k][32 + ty * 4];
            unsigned long long b0 = bcast2(w0.x), b1 = bcast2(w0.y);
            unsigned long long b2 = bcast2(w0.z), b3 = bcast2(w0.w);
            unsigned long long b4 = bcast2(w1.x), b5 = bcast2(w1.y);
            unsigned long long b6 = bcast2(w1.z), b7 = bcast2(w1.w);

            fma2(acc[0][0], A0.x, b0); fma2(acc[0][1], A0.y, b0);
            fma2(acc[0][2], A1.x, b0); fma2(acc[0][3], A1.y, b0);
            fma2(acc[1][0], A0.x, b1); fma2(acc[1][1], A0.y, b1);
            fma2(acc[1][2], A1.x, b1); fma2(acc[1][3], A1.y, b1);
            fma2(acc[2][0], A0.x, b2); fma2(acc[2][1], A0.y, b2);
            fma2(acc[2][2], A1.x, b2); fma2(acc[2][3], A1.y, b2);
            fma2(acc[3][0], A0.x, b3); fma2(acc[3][1], A0.y, b3);
            fma2(acc[3][2], A1.x, b3); fma2(acc[3][3], A1.y, b3);
            fma2(acc[4][0], A0.x, b4); fma2(acc[4][1], A0.y, b4);
            fma2(acc[4][2], A1.x, b4); fma2(acc[4][3], A1.y, b4);
            fma2(acc[5][0], A0.x, b5); fma2(acc[5][1], A0.y, b5);
            fma2(acc[5][2], A1.x, b5); fma2(acc[5][3], A1.y, b5);
            fma2(acc[6][0], A0.x, b6); fma2(acc[6][1], A0.y, b6);
            fma2(acc[6][2], A1.x, b6); fma2(acc[6][3], A1.y, b6);
            fma2(acc[7][0], A0.x, b7); fma2(acc[7][1], A0.y, b7);
            fma2(acc[7][2], A1.x, b7); fma2(acc[7][3], A1.y, b7);
        }
        __syncthreads();
    }

    // epilogue: each (expert, token-group) is 4 consecutive tokens -> 16B store
    #pragma unroll
    for (int eg = 0; eg < 2; eg++) {
        #pragma unroll
        for (int e = 0; e < 4; e++) {
            int eglob = eg * 32 + ty * 4 + e;
            float* base = &g_aff[(size_t)eglob * NTOK + n0];
            ulonglong2 v0, v1;
            v0.x = acc[eg * 4 + e][0]; v0.y = acc[eg * 4 + e][1];
            v1.x = acc[eg * 4 + e][2]; v1.y = acc[eg * 4 + e][3];
            *(ulonglong2*)&base[tx * 4]      = v0;
            *(ulonglong2*)&base[64 + tx * 4] = v1;
        }
    }
}

// ---------------- per-expert top-256 + softmax (exact fp32 radix select) ----------
__device__ __forceinline__ unsigned f2key(float v) {
    unsigned u = __float_as_uint(v);
    return (u & 0x80000000u) ? ~u : (u | 0x80000000u);
}

__global__ __launch_bounds__(256) void topk_kernel() {
    const int e   = blockIdx.x;
    const int tid = threadIdx.x;
    const float* __restrict__ row = g_aff + (size_t)e * NTOK;

    __shared__ unsigned hist[2048];
    __shared__ unsigned chunksum[257];
    __shared__ unsigned sh_prefix, sh_kneed, sh_bin, sh_above;
    __shared__ int   s_idx[CAP];
    __shared__ float s_val[CAP];
    __shared__ int   tie_buf[64];
    __shared__ int   sel_n, tie_n;
    __shared__ float red[10];

    if (tid == 0) { sh_prefix = 0u; sh_kneed = CAP; sel_n = 0; tie_n = 0; }

    const int      shifts[3]   = {21, 10, 0};
    const unsigned binmask[3]  = {2047u, 2047u, 1023u};
    const unsigned donemask[3] = {0u, 0xFFE00000u, 0xFFFFFC00u};

    for (int r = 0; r < 3; r++) {
        for (int b = tid; b < 2048; b += 256) hist[b] = 0u;
        __syncthreads();

        const unsigned pfx = sh_prefix;
        const unsigned dm  = donemask[r];
        const int      sh  = shifts[r];
        const unsigned bm  = binmask[r];

        #pragma unroll 4
        for (int j = 0; j < NTOK / 256; j++) {
            unsigned key = f2key(row[tid + j * 256]);
            if ((key & dm) == pfx) atomicAdd(&hist[(key >> sh) & bm], 1u);
        }
        __syncthreads();

        unsigned S = 0;
        #pragma unroll
        for (int q = 0; q < 8; q++) S += hist[tid * 8 + q];
        chunksum[tid] = S;
        __syncthreads();
        for (int off = 1; off < 256; off <<= 1) {
            unsigned v = (tid + off < 256) ? chunksum[tid + off] : 0u;
            __syncthreads();
            chunksum[tid] += v;
            __syncthreads();
        }
        const unsigned kneed = sh_kneed;
        unsigned above = (tid < 255) ? chunksum[tid + 1] : 0u;
        for (int b = tid * 8 + 7; b >= tid * 8; b--) {
            unsigned h = hist[b];
            if (kneed > above && kneed <= above + h) { sh_bin = (unsigned)b; sh_above = above; }
            above += h;
        }
        __syncthreads();
        if (tid == 0) {
            sh_prefix |= (sh_bin << shifts[r]);
            sh_kneed  -= sh_above;
        }
    }
    __syncthreads();
    const unsigned T    = sh_prefix;
    const unsigned krem = sh_kneed;

    #pragma unroll 4
    for (int j = 0; j < NTOK / 256; j++) {
        int i = tid + j * 256;
        float v = row[i];
        unsigned key = f2key(v);
        if (key > T) {
            int p = atomicAdd(&sel_n, 1);
            s_idx[p] = i; s_val[p] = v;
        } else if (key == T) {
            int p = atomicAdd(&tie_n, 1);
            if (p < 64) tie_buf[p] = i;
        }
    }
    __syncthreads();
    int tn = tie_n; if (tn > 64) tn = 64;
    if (tid < tn) {
        int my = tie_buf[tid], rank = 0;
        for (int j = 0; j < tn; j++) rank += (tie_buf[j] < my);
        if (rank < (int)krem) {
            int p = atomicAdd(&sel_n, 1);
            s_idx[p] = my; s_val[p] = row[my];
        }
    }
    __syncthreads();

    // softmax over the 256 selected scores
    float v = s_val[tid];
    float m = v;
    #pragma unroll
    for (int o = 16; o; o >>= 1) m = fmaxf(m, __shfl_xor_sync(0xffffffffu, m, o));
    if ((tid & 31) == 0) red[tid >> 5] = m;
    __syncthreads();
    if (tid == 0) {
        float t = red[0];
        #pragma unroll
        for (int i = 1; i < 8; i++) t = fmaxf(t, red[i]);
        red[8] = t;
    }
    __syncthreads();
    float ex = expf(v - red[8]);
    float s = ex;
    #pragma unroll
    for (int o = 16; o; o >>= 1) s += __shfl_xor_sync(0xffffffffu, s, o);
    if ((tid & 31) == 0) red[tid >> 5] = s;
    __syncthreads();
    if (tid == 0) {
        float t = 0.f;
        #pragma unroll
        for (int i = 0; i < 8; i++) t += red[i];
        red[9] = t;
    }
    __syncthreads();
    float prob = ex / red[9];

    g_sel_idx[e * CAP + tid]  = s_idx[tid];
    g_sel_prob[e * CAP + tid] = prob;
    atomicAdd(&g_counts[s_idx[tid]], 1);
}

// ---------------- output fill (zeros + capacity tail) + counts reset ----------------
__global__ void fill_kernel(float* __restrict__ out, long long out_size) {
    long long g = (long long)blockIdx.x * blockDim.x + threadIdx.x;
    long long stride = (long long)gridDim.x * blockDim.x;
    const long long NE2 = 2LL * NTOK * NEXP;

    float4 z4 = make_float4(0.f, 0.f, 0.f, 0.f);
    float4* o4 = (float4*)out;
    long long n4 = NE2 >> 2;
    long long lim4 = (out_size >> 2) < n4 ? (out_size >> 2) : n4;
    for (long long i = g; i < lim4; i += stride) o4[i] = z4;
    for (long long i = NE2 + g; i < out_size; i += stride) out[i] = (float)CAP;

    for (long long i = g; i < NTOK; i += stride) g_counts[i] = 0;
}

// ---------------- scatter: weights = prob/count, assignments = 1 ----------------
__global__ void scatter_kernel(float* __restrict__ out) {
    int idx = blockIdx.x * blockDim.x + threadIdx.x;   // 0 .. E*CAP-1
    int e = idx >> 8;
    int n = g_sel_idx[idx];
    float p = g_sel_prob[idx];
    int c = g_counts[n];
    out[(size_t)n * NEXP + e] = p / (float)c;
    out[(size_t)NTOK * NEXP + (size_t)n * NEXP + e] = 1.0f;
}

// ---------------- launch ----------------
extern "C" void kernel_launch(void* const* d_in, const int* in_sizes, int n_in,
                              void* d_out, int out_size) {
    (void)in_sizes; (void)n_in;
    const float* hs = (const float*)d_in[0];   // hidden_states [4,4096,2048] fp32
    const float* ws = (const float*)d_in[1];   // w_sel [64,2048] fp32
    float* out = (float*)d_out;

    fill_kernel<<<2048, 256>>>(out, (long long)out_size);
    gemm_kernel<<<NTOK / BT, 128>>>(hs, ws);
    topk_kernel<<<NEXP, 256>>>();
    scatter_kernel<<<NEXP * CAP / 256, 256>>>(out);
}

// round 6
// speedup vs baseline: 1.2367x; 1.1699x over previous
#include <cuda_runtime.h>
#include <math.h>
#include <stdint.h>

#define NTOK 16384
#define DDIM 2048
#define NEXP 64
#define CAP  256

// GEMM tiling (legacy mma.sync tf32 path, compute_100-compatible)
#define BT   128                 // tokens per CTA
#define KC   32                  // K per chunk
#define NC   (DDIM / KC)         // 64 chunks
#define KS   44                  // padded row stride (floats): 176B, 16B-aligned, conflict-free
#define A_TILE_B (BT * KS * 4)           // 22528
#define B_TILE_B (NEXP * KS * 4)         // 11264
#define OFF_AHI  0
#define OFF_ALO  (A_TILE_B)
#define OFF_BHI  (2 * A_TILE_B)
#define OFF_BLO  (2 * A_TILE_B + B_TILE_B)
#define STAGE_B  (2 * A_TILE_B + 2 * B_TILE_B)   // 67584
#define SMEM_DYN (2 * STAGE_B)                    // 135168

// ---------------- scratch (static device globals: allocation-free) ----------------
__device__ __align__(16) float g_aff[NEXP * NTOK];      // affinity [e][n], 4 MB
__device__ int   g_counts[NTOK];
__device__ int   g_sel_idx[NEXP * CAP];
__device__ float g_sel_prob[NEXP * CAP];

// ---------------- helpers ----------------
__device__ __forceinline__ void cvt_split(float a, uint32_t &hi, float &lo) {
    asm("cvt.rna.tf32.f32 %0, %1;" : "=r"(hi) : "f"(a));
    lo = a - __uint_as_float(hi);
}
__device__ __forceinline__ void mma_tf32(float* d, const uint32_t* a, const uint32_t* b) {
    asm volatile("mma.sync.aligned.m16n8k8.row.col.f32.tf32.tf32.f32 "
        "{%0,%1,%2,%3}, {%4,%5,%6,%7}, {%8,%9}, {%0,%1,%2,%3};"
        : "+f"(d[0]), "+f"(d[1]), "+f"(d[2]), "+f"(d[3])
        : "r"(a[0]), "r"(a[1]), "r"(a[2]), "r"(a[3]), "r"(b[0]), "r"(b[1]));
}

// ---------------- GEMM: aff[e][n] = sum_d tok[n][d] * wsel[e][d] (3xTF32 mma.sync) ----
__global__ __launch_bounds__(256, 1)
void gemm_tc_kernel(const float* __restrict__ tok, const float* __restrict__ wsel) {
    extern __shared__ __align__(16) char dyn[];

    const int tid  = threadIdx.x;
    const int lane = tid & 31;
    const int w    = tid >> 5;           // 8 warps
    const int n0   = blockIdx.x * BT;

    const int wm = (w & 3) * 32;         // warp token base
    const int wn = (w >> 2) * 32;        // warp expert base
    const int gr = lane >> 2;            // 0..7
    const int ci = lane & 3;             // 0..3

    // accumulators: d[mt][nt][4]
    float d[2][4][4];
    #pragma unroll
    for (int mt = 0; mt < 2; mt++)
        #pragma unroll
        for (int nt = 0; nt < 4; nt++)
            #pragma unroll
            for (int r = 0; r < 4; r++) d[mt][nt][r] = 0.f;

    // staging assignment: A rows tTok+32j (j=0..3), q = k-quad; B: 2 passes over 64 rows
    const int tTok = tid >> 3;
    const int qA   = tid & 7;

    float4 rA[4], rB[2];
    #pragma unroll
    for (int j = 0; j < 4; j++)
        rA[j] = *(const float4*)&tok[(size_t)(n0 + tTok + 32 * j) * DDIM + qA * 4];
    #pragma unroll
    for (int j = 0; j < 2; j++) {
        int i = tid + 256 * j;
        rB[j] = *(const float4*)&wsel[(size_t)(i >> 3) * DDIM + (i & 7) * 4];
    }

    // stage chunk 0
    {
        char* s0 = dyn;
        #pragma unroll
        for (int j = 0; j < 4; j++) {
            uint4 h; float4 l;
            cvt_split(rA[j].x, h.x, l.x); cvt_split(rA[j].y, h.y, l.y);
            cvt_split(rA[j].z, h.z, l.z); cvt_split(rA[j].w, h.w, l.w);
            int off = ((tTok + 32 * j) * KS + qA * 4) * 4;
            *(uint4*)(s0 + OFF_AHI + off)  = h;
            *(float4*)(s0 + OFF_ALO + off) = l;
        }
        #pragma unroll
        for (int j = 0; j < 2; j++) {
            int i = tid + 256 * j;
            uint4 h; float4 l;
            cvt_split(rB[j].x, h.x, l.x); cvt_split(rB[j].y, h.y, l.y);
            cvt_split(rB[j].z, h.z, l.z); cvt_split(rB[j].w, h.w, l.w);
            int off = ((i >> 3) * KS + (i & 7) * 4) * 4;
            *(uint4*)(s0 + OFF_BHI + off)  = h;
            *(float4*)(s0 + OFF_BLO + off) = l;
        }
    }
    __syncthreads();

    for (int c = 0; c < NC; c++) {
        // prefetch next chunk into regs
        if (c + 1 < NC) {
            int db = (c + 1) * KC;
            #pragma unroll
            for (int j = 0; j < 4; j++)
                rA[j] = *(const float4*)&tok[(size_t)(n0 + tTok + 32 * j) * DDIM + db + qA * 4];
            #pragma unroll
            for (int j = 0; j < 2; j++) {
                int i = tid + 256 * j;
                rB[j] = *(const float4*)&wsel[(size_t)(i >> 3) * DDIM + db + (i & 7) * 4];
            }
        }

        // compute on stage c&1
        {
            const char* sb = dyn + (c & 1) * STAGE_B;
            const uint32_t* sAhi = (const uint32_t*)(sb + OFF_AHI);
            const uint32_t* sAlo = (const uint32_t*)(sb + OFF_ALO);
            const uint32_t* sBhi = (const uint32_t*)(sb + OFF_BHI);
            const uint32_t* sBlo = (const uint32_t*)(sb + OFF_BLO);

            #pragma unroll
            for (int k8 = 0; k8 < KC / 8; k8++) {
                const int kb = k8 * 8;
                uint32_t ah[2][4], al[2][4], bh[4][2], bl[4][2];
                #pragma unroll
                for (int mt = 0; mt < 2; mt++) {
                    int r0 = (wm + mt * 16 + gr) * KS + kb + ci;
                    int r8 = r0 + 8 * KS;
                    ah[mt][0] = sAhi[r0];     ah[mt][1] = sAhi[r8];
                    ah[mt][2] = sAhi[r0 + 4]; ah[mt][3] = sAhi[r8 + 4];
                    al[mt][0] = sAlo[r0];     al[mt][1] = sAlo[r8];
                    al[mt][2] = sAlo[r0 + 4]; al[mt][3] = sAlo[r8 + 4];
                }
                #pragma unroll
                for (int nt = 0; nt < 4; nt++) {
                    int b0 = (wn + nt * 8 + gr) * KS + kb + ci;
                    bh[nt][0] = sBhi[b0]; bh[nt][1] = sBhi[b0 + 4];
                    bl[nt][0] = sBlo[b0]; bl[nt][1] = sBlo[b0 + 4];
                }
                #pragma unroll
                for (int mt = 0; mt < 2; mt++)
                    #pragma unroll
                    for (int nt = 0; nt < 4; nt++) {
                        mma_tf32(d[mt][nt], ah[mt], bh[nt]);
                        mma_tf32(d[mt][nt], ah[mt], bl[nt]);
                        mma_tf32(d[mt][nt], al[mt], bh[nt]);
                    }
            }
        }

        // stage next chunk into the other buffer (read by nobody this iter)
        if (c + 1 < NC) {
            char* sn = dyn + ((c + 1) & 1) * STAGE_B;
            #pragma unroll
            for (int j = 0; j < 4; j++) {
                uint4 h; float4 l;
                cvt_split(rA[j].x, h.x, l.x); cvt_split(rA[j].y, h.y, l.y);
                cvt_split(rA[j].z, h.z, l.z); cvt_split(rA[j].w, h.w, l.w);
                int off = ((tTok + 32 * j) * KS + qA * 4) * 4;
                *(uint4*)(sn + OFF_AHI + off)  = h;
                *(float4*)(sn + OFF_ALO + off) = l;
            }
            #pragma unroll
            for (int j = 0; j < 2; j++) {
                int i = tid + 256 * j;
                uint4 h; float4 l;
                cvt_split(rB[j].x, h.x, l.x); cvt_split(rB[j].y, h.y, l.y);
                cvt_split(rB[j].z, h.z, l.z); cvt_split(rB[j].w, h.w, l.w);
                int off = ((i >> 3) * KS + (i & 7) * 4) * 4;
                *(uint4*)(sn + OFF_BHI + off)  = h;
                *(float4*)(sn + OFF_BLO + off) = l;
            }
            __syncthreads();
        }
    }

    // epilogue: d[mt][nt] -> g_aff[e][token]
    #pragma unroll
    for (int mt = 0; mt < 2; mt++) {
        int tok0 = n0 + wm + mt * 16 + gr;
        #pragma unroll
        for (int nt = 0; nt < 4; nt++) {
            int e0 = wn + nt * 8 + 2 * ci;
            g_aff[(size_t)e0 * NTOK + tok0]           = d[mt][nt][0];
            g_aff[(size_t)(e0 + 1) * NTOK + tok0]     = d[mt][nt][1];
            g_aff[(size_t)e0 * NTOK + tok0 + 8]       = d[mt][nt][2];
            g_aff[(size_t)(e0 + 1) * NTOK + tok0 + 8] = d[mt][nt][3];
        }
    }
}

// ---------------- per-expert top-256 + softmax (exact fp32 radix select) ----------
__device__ __forceinline__ unsigned f2key(float v) {
    unsigned u = __float_as_uint(v);
    return (u & 0x80000000u) ? ~u : (u | 0x80000000u);
}

__global__ __launch_bounds__(256) void topk_kernel() {
    const int e   = blockIdx.x;
    const int tid = threadIdx.x;
    const float* __restrict__ row = g_aff + (size_t)e * NTOK;

    __shared__ unsigned hist[2048];
    __shared__ unsigned chunksum[257];
    __shared__ unsigned sh_prefix, sh_kneed, sh_bin, sh_above;
    __shared__ int   s_idx[CAP];
    __shared__ float s_val[CAP];
    __shared__ int   tie_buf[64];
    __shared__ int   sel_n, tie_n;
    __shared__ float red[10];

    if (tid == 0) { sh_prefix = 0u; sh_kneed = CAP; sel_n = 0; tie_n = 0; }

    const int      shifts[3]   = {21, 10, 0};
    const unsigned binmask[3]  = {2047u, 2047u, 1023u};
    const unsigned donemask[3] = {0u, 0xFFE00000u, 0xFFFFFC00u};

    for (int r = 0; r < 3; r++) {
        for (int b = tid; b < 2048; b += 256) hist[b] = 0u;
        __syncthreads();

        const unsigned pfx = sh_prefix;
        const unsigned dm  = donemask[r];
        const int      sh  = shifts[r];
        const unsigned bm  = binmask[r];

        #pragma unroll 4
        for (int j = 0; j < NTOK / 256; j++) {
            unsigned key = f2key(row[tid + j * 256]);
            if ((key & dm) == pfx) atomicAdd(&hist[(key >> sh) & bm], 1u);
        }
        __syncthreads();

        unsigned S = 0;
        #pragma unroll
        for (int q = 0; q < 8; q++) S += hist[tid * 8 + q];
        chunksum[tid] = S;
        __syncthreads();
        for (int off = 1; off < 256; off <<= 1) {
            unsigned v = (tid + off < 256) ? chunksum[tid + off] : 0u;
            __syncthreads();
            chunksum[tid] += v;
            __syncthreads();
        }
        const unsigned kneed = sh_kneed;
        unsigned above = (tid < 255) ? chunksum[tid + 1] : 0u;
        for (int b = tid * 8 + 7; b >= tid * 8; b--) {
            unsigned h = hist[b];
            if (kneed > above && kneed <= above + h) { sh_bin = (unsigned)b; sh_above = above; }
            above += h;
        }
        __syncthreads();
        if (tid == 0) {
            sh_prefix |= (sh_bin << shifts[r]);
            sh_kneed  -= sh_above;
        }
    }
    __syncthreads();
    const unsigned T    = sh_prefix;
    const unsigned krem = sh_kneed;

    #pragma unroll 4
    for (int j = 0; j < NTOK / 256; j++) {
        int i = tid + j * 256;
        float v = row[i];
        unsigned key = f2key(v);
        if (key > T) {
            int p = atomicAdd(&sel_n, 1);
            s_idx[p] = i; s_val[p] = v;
        } else if (key == T) {
            int p = atomicAdd(&tie_n, 1);
            if (p < 64) tie_buf[p] = i;
        }
    }
    __syncthreads();
    int tn = tie_n; if (tn > 64) tn = 64;
    if (tid < tn) {
        int my = tie_buf[tid], rank = 0;
        for (int j = 0; j < tn; j++) rank += (tie_buf[j] < my);
        if (rank < (int)krem) {
            int p = atomicAdd(&sel_n, 1);
            s_idx[p] = my; s_val[p] = row[my];
        }
    }
    __syncthreads();

    // softmax over the 256 selected scores
    float v = s_val[tid];
    float m = v;
    #pragma unroll
    for (int o = 16; o; o >>= 1) m = fmaxf(m, __shfl_xor_sync(0xffffffffu, m, o));
    if ((tid & 31) == 0) red[tid >> 5] = m;
    __syncthreads();
    if (tid == 0) {
        float t = red[0];
        #pragma unroll
        for (int i = 1; i < 8; i++) t = fmaxf(t, red[i]);
        red[8] = t;
    }
    __syncthreads();
    float ex = expf(v - red[8]);
    float s = ex;
    #pragma unroll
    for (int o = 16; o; o >>= 1) s += __shfl_xor_sync(0xffffffffu, s, o);
    if ((tid & 31) == 0) red[tid >> 5] = s;
    __syncthreads();
    if (tid == 0) {
        float t = 0.f;
        #pragma unroll
        for (int i = 0; i < 8; i++) t += red[i];
        red[9] = t;
    }
    __syncthreads();
    float prob = ex / red[9];

    g_sel_idx[e * CAP + tid]  = s_idx[tid];
    g_sel_prob[e * CAP + tid] = prob;
    atomicAdd(&g_counts[s_idx[tid]], 1);
}

// ---------------- output fill (zeros + capacity tail) + counts reset ----------------
__global__ void fill_kernel(float* __restrict__ out, long long out_size) {
    long long g = (long long)blockIdx.x * blockDim.x + threadIdx.x;
    long long stride = (long long)gridDim.x * blockDim.x;
    const long long NE2 = 2LL * NTOK * NEXP;

    float4 z4 = make_float4(0.f, 0.f, 0.f, 0.f);
    float4* o4 = (float4*)out;
    long long n4 = NE2 >> 2;
    long long lim4 = (out_size >> 2) < n4 ? (out_size >> 2) : n4;
    for (long long i = g; i < lim4; i += stride) o4[i] = z4;
    for (long long i = NE2 + g; i < out_size; i += stride) out[i] = (float)CAP;

    for (long long i = g; i < NTOK; i += stride) g_counts[i] = 0;
}

// ---------------- scatter: weights = prob/count, assignments = 1 ----------------
__global__ void scatter_kernel(float* __restrict__ out) {
    int idx = blockIdx.x * blockDim.x + threadIdx.x;   // 0 .. E*CAP-1
    int e = idx >> 8;
    int n = g_sel_idx[idx];
    float p = g_sel_prob[idx];
    int c = g_counts[n];
    out[(size_t)n * NEXP + e] = p / (float)c;
    out[(size_t)NTOK * NEXP + (size_t)n * NEXP + e] = 1.0f;
}

// ---------------- launch ----------------
extern "C" void kernel_launch(void* const* d_in, const int* in_sizes, int n_in,
                              void* d_out, int out_size) {
    (void)in_sizes; (void)n_in;
    const float* hs = (const float*)d_in[0];   // hidden_states [4,4096,2048] fp32
    const float* ws = (const float*)d_in[1];   // w_sel [64,2048] fp32
    float* out = (float*)d_out;

    static int cfg_done = 0;
    if (!cfg_done) {
        cudaFuncSetAttribute(gemm_tc_kernel, cudaFuncAttributeMaxDynamicSharedMemorySize,
                             SMEM_DYN);
        cfg_done = 1;
    }

    fill_kernel<<<2048, 256>>>(out, (long long)out_size);
    gemm_tc_kernel<<<NTOK / BT, 256, SMEM_DYN>>>(hs, ws);
    topk_kernel<<<NEXP, 256>>>();
    scatter_kernel<<<NEXP * CAP / 256, 256>>>(out);
}

// round 7
// speedup vs baseline: 1.6485x; 1.3330x over previous
#include <cuda_runtime.h>
#include <math.h>
#include <stdint.h>

#define NTOK 16384
#define DDIM 2048
#define NEXP 64
#define CAP  256

// GEMM tiling (int8 limb-emulation via legacy mma.sync, compute_100-compatible)
#define BT   128                  // tokens per CTA
#define KC   32                   // K elements per chunk = one k32 mma step
#define NC   (DDIM / KC)          // 64 chunks
#define A_PLANE_W 1024            // 128 rows x 8 words per limb plane
#define B_PLANE_W 512             // 64 rows x 8 words
#define STAGE_W   (3 * A_PLANE_W + 3 * B_PLANE_W)   // 4608 words = 18 KB

#define SA 1048576.0f             // 2^20 token scale
#define SB 16777216.0f            // 2^24 w_sel scale
#define QCLAMP 8355711.0f         // 127*65536 + 127*256 + 127

// ---------------- scratch (static device globals: allocation-free) ----------------
__device__ __align__(16) float g_aff[NEXP * NTOK];      // affinity [e][n], 4 MB
__device__ int   g_counts[NTOK];
__device__ int   g_sel_idx[NEXP * CAP];
__device__ float g_sel_prob[NEXP * CAP];

// ---------------- helpers ----------------
__device__ __forceinline__ void q3(float a, float scale, int &m0, int &m1, int &m2) {
    float af = fminf(fmaxf(a * scale, -QCLAMP), QCLAMP);
    int m = __float2int_rn(af);
    m2 = ((m + 128) & 255) - 128;
    int t = (m - m2) >> 8;
    m1 = ((t + 128) & 255) - 128;
    m0 = (t - m1) >> 8;
}
__device__ __forceinline__ uint32_t pack4(int b0, int b1, int b2, int b3) {
    return (uint32_t)(b0 & 255) | ((uint32_t)(b1 & 255) << 8) |
           ((uint32_t)(b2 & 255) << 16) | ((uint32_t)b3 << 24);
}
// stage one float4 (4 consecutive K elems) into the 3 limb planes at word index wi
__device__ __forceinline__ void quant_store(float4 v, float scale,
                                            uint32_t* p0, uint32_t* p1, uint32_t* p2,
                                            uint32_t wi) {
    int a0,a1,a2, b0,b1,b2, c0,c1,c2, d0,d1,d2;
    q3(v.x, scale, a0, a1, a2);
    q3(v.y, scale, b0, b1, b2);
    q3(v.z, scale, c0, c1, c2);
    q3(v.w, scale, d0, d1, d2);
    p0[wi] = pack4(a0, b0, c0, d0);
    p1[wi] = pack4(a1, b1, c1, d1);
    p2[wi] = pack4(a2, b2, c2, d2);
}
__device__ __forceinline__ void imma(int* d, const uint32_t* a, const uint32_t* b) {
    asm volatile("mma.sync.aligned.m16n8k32.row.col.s32.s8.s8.s32 "
        "{%0,%1,%2,%3}, {%4,%5,%6,%7}, {%8,%9}, {%0,%1,%2,%3};"
        : "+r"(d[0]), "+r"(d[1]), "+r"(d[2]), "+r"(d[3])
        : "r"(a[0]), "r"(a[1]), "r"(a[2]), "r"(a[3]), "r"(b[0]), "r"(b[1]));
}

// ---------------- GEMM: aff[e][n] = sum_d tok[n][d] * wsel[e][d] (int8 limbs) ----
// 512 threads, warp grid 4(m) x 4(n), warp tile 32 tok x 16 exp, mt=2 nt=2.
__global__ __launch_bounds__(512, 1)
void gemm_imma_kernel(const float* __restrict__ tok, const float* __restrict__ wsel) {
    __shared__ __align__(16) uint32_t smem[2 * STAGE_W];   // 36 KB

    const int tid  = threadIdx.x;
    const int lane = tid & 31;
    const int w    = tid >> 5;            // 16 warps
    const int n0   = blockIdx.x * BT;
    const int gr   = lane >> 2;           // 0..7
    const int ci   = lane & 3;            // 0..3
    const int wm   = (w & 3) * 32;        // warp token base
    const int wn   = (w >> 2) * 16;       // warp expert base
    const int w0   = ci ^ gr;             // swizzled word (k 0..15 half)
    const int w1   = (ci + 4) ^ gr;       // swizzled word (k 16..31 half)

    int hh[2][2][4], md[2][2][4], lo[2][2][4];
    #pragma unroll
    for (int mt = 0; mt < 2; mt++)
        #pragma unroll
        for (int nt = 0; nt < 2; nt++)
            #pragma unroll
            for (int r = 0; r < 4; r++) { hh[mt][nt][r] = 0; md[mt][nt][r] = 0; lo[mt][nt][r] = 0; }

    // staging assignment: r = tid>>3 (0..63), q = tid&7 (k-quad)
    const int rr = tid >> 3;
    const int qq = tid & 7;
    const uint32_t swi = (uint32_t)(rr * 8 + (qq ^ (rr & 7)));        // A row rr / B row rr
    const uint32_t swi2 = (uint32_t)((rr + 64) * 8 + (qq ^ (rr & 7))); // A row rr+64 (same swizzle class)

    const float* gA0 = &tok[(size_t)(n0 + rr) * DDIM + qq * 4];
    const float* gA1 = &tok[(size_t)(n0 + rr + 64) * DDIM + qq * 4];
    const float* gB  = &wsel[(size_t)rr * DDIM + qq * 4];

    float4 rA0 = *(const float4*)gA0;
    float4 rA1 = *(const float4*)gA1;
    float4 rB  = *(const float4*)gB;

    // stage chunk 0 into buffer 0
    {
        uint32_t* sb = smem;
        quant_store(rA0, SA, sb, sb + A_PLANE_W, sb + 2 * A_PLANE_W, swi);
        quant_store(rA1, SA, sb, sb + A_PLANE_W, sb + 2 * A_PLANE_W, swi2);
        uint32_t* pb = sb + 3 * A_PLANE_W;
        quant_store(rB, SB, pb, pb + B_PLANE_W, pb + 2 * B_PLANE_W, swi);
    }
    __syncthreads();

    for (int c = 0; c < NC; c++) {
        // prefetch next chunk into regs
        if (c + 1 < NC) {
            rA0 = *(const float4*)(gA0 + (c + 1) * KC);
            rA1 = *(const float4*)(gA1 + (c + 1) * KC);
            rB  = *(const float4*)(gB  + (c + 1) * KC);
        }

        // compute on stage c&1
        {
            const uint32_t* sb = smem + (c & 1) * STAGE_W;
            const uint32_t* pb = sb + 3 * A_PLANE_W;

            uint32_t af[2][3][4];
            #pragma unroll
            for (int mt = 0; mt < 2; mt++) {
                const int r0 = (wm + mt * 16 + gr) * 8;
                #pragma unroll
                for (int L = 0; L < 3; L++) {
                    const uint32_t* p = sb + L * A_PLANE_W;
                    af[mt][L][0] = p[r0 + w0];
                    af[mt][L][1] = p[r0 + 64 + w0];   // +8 rows
                    af[mt][L][2] = p[r0 + w1];
                    af[mt][L][3] = p[r0 + 64 + w1];
                }
            }
            #pragma unroll
            for (int nt = 0; nt < 2; nt++) {
                const int c0 = (wn + nt * 8 + gr) * 8;
                uint32_t bf[3][2];
                #pragma unroll
                for (int L = 0; L < 3; L++) {
                    const uint32_t* p = pb + L * B_PLANE_W;
                    bf[L][0] = p[c0 + w0];
                    bf[L][1] = p[c0 + w1];
                }
                #pragma unroll
                for (int mt = 0; mt < 2; mt++) {
                    imma(hh[mt][nt], af[mt][0], bf[0]);
                    imma(md[mt][nt], af[mt][0], bf[1]);
                    imma(md[mt][nt], af[mt][1], bf[0]);
                    imma(lo[mt][nt], af[mt][0], bf[2]);
                    imma(lo[mt][nt], af[mt][1], bf[1]);
                    imma(lo[mt][nt], af[mt][2], bf[0]);
                }
            }
        }

        // stage next chunk into the other buffer
        if (c + 1 < NC) {
            uint32_t* sn = smem + ((c + 1) & 1) * STAGE_W;
            quant_store(rA0, SA, sn, sn + A_PLANE_W, sn + 2 * A_PLANE_W, swi);
            quant_store(rA1, SA, sn, sn + A_PLANE_W, sn + 2 * A_PLANE_W, swi2);
            uint32_t* pn = sn + 3 * A_PLANE_W;
            quant_store(rB, SB, pn, pn + B_PLANE_W, pn + 2 * B_PLANE_W, swi);
            __syncthreads();
        }
    }

    // epilogue: dequant and write g_aff[e][token]
    #pragma unroll
    for (int mt = 0; mt < 2; mt++) {
        const int tok0 = n0 + wm + mt * 16 + gr;
        #pragma unroll
        for (int nt = 0; nt < 2; nt++) {
            const int e0 = wn + nt * 8 + 2 * ci;
            #pragma unroll
            for (int r = 0; r < 4; r++) {
                float v = fmaf((float)hh[mt][nt][r], 0x1p-12f,
                          fmaf((float)md[mt][nt][r], 0x1p-20f,
                               (float)lo[mt][nt][r] * 0x1p-28f));
                const int tk = tok0 + ((r >> 1) << 3);   // +8 for r=2,3
                const int ee = e0 + (r & 1);
                g_aff[(size_t)ee * NTOK + tk] = v;
            }
        }
    }
}

// ---------------- per-expert top-256 + softmax (exact fp32 radix select) ----------
__device__ __forceinline__ unsigned f2key(float v) {
    unsigned u = __float_as_uint(v);
    return (u & 0x80000000u) ? ~u : (u | 0x80000000u);
}

__global__ __launch_bounds__(256) void topk_kernel() {
    const int e   = blockIdx.x;
    const int tid = threadIdx.x;
    const float* __restrict__ row = g_aff + (size_t)e * NTOK;

    __shared__ unsigned hist[2048];
    __shared__ unsigned chunksum[257];
    __shared__ unsigned sh_prefix, sh_kneed, sh_bin, sh_above;
    __shared__ int   s_idx[CAP];
    __shared__ float s_val[CAP];
    __shared__ int   tie_buf[64];
    __shared__ int   sel_n, tie_n;
    __shared__ float red[10];

    if (tid == 0) { sh_prefix = 0u; sh_kneed = CAP; sel_n = 0; tie_n = 0; }

    const int      shifts[3]   = {21, 10, 0};
    const unsigned binmask[3]  = {2047u, 2047u, 1023u};
    const unsigned donemask[3] = {0u, 0xFFE00000u, 0xFFFFFC00u};

    for (int r = 0; r < 3; r++) {
        for (int b = tid; b < 2048; b += 256) hist[b] = 0u;
        __syncthreads();

        const unsigned pfx = sh_prefix;
        const unsigned dm  = donemask[r];
        const int      sh  = shifts[r];
        const unsigned bm  = binmask[r];

        #pragma unroll 4
        for (int j = 0; j < NTOK / 256; j++) {
            unsigned key = f2key(row[tid + j * 256]);
            if ((key & dm) == pfx) atomicAdd(&hist[(key >> sh) & bm], 1u);
        }
        __syncthreads();

        unsigned S = 0;
        #pragma unroll
        for (int q = 0; q < 8; q++) S += hist[tid * 8 + q];
        chunksum[tid] = S;
        __syncthreads();
        for (int off = 1; off < 256; off <<= 1) {
            unsigned v = (tid + off < 256) ? chunksum[tid + off] : 0u;
            __syncthreads();
            chunksum[tid] += v;
            __syncthreads();
        }
        const unsigned kneed = sh_kneed;
        unsigned above = (tid < 255) ? chunksum[tid + 1] : 0u;
        for (int b = tid * 8 + 7; b >= tid * 8; b--) {
            unsigned h = hist[b];
            if (kneed > above && kneed <= above + h) { sh_bin = (unsigned)b; sh_above = above; }
            above += h;
        }
        __syncthreads();
        if (tid == 0) {
            sh_prefix |= (sh_bin << shifts[r]);
            sh_kneed  -= sh_above;
        }
    }
    __syncthreads();
    const unsigned T    = sh_prefix;
    const unsigned krem = sh_kneed;

    #pragma unroll 4
    for (int j = 0; j < NTOK / 256; j++) {
        int i = tid + j * 256;
        float v = row[i];
        unsigned key = f2key(v);
        if (key > T) {
            int p = atomicAdd(&sel_n, 1);
            s_idx[p] = i; s_val[p] = v;
        } else if (key == T) {
            int p = atomicAdd(&tie_n, 1);
            if (p < 64) tie_buf[p] = i;
        }
    }
    __syncthreads();
    int tn = tie_n; if (tn > 64) tn = 64;
    if (tid < tn) {
        int my = tie_buf[tid], rank = 0;
        for (int j = 0; j < tn; j++) rank += (tie_buf[j] < my);
        if (rank < (int)krem) {
            int p = atomicAdd(&sel_n, 1);
            s_idx[p] = my; s_val[p] = row[my];
        }
    }
    __syncthreads();

    // softmax over the 256 selected scores
    float v = s_val[tid];
    float m = v;
    #pragma unroll
    for (int o = 16; o; o >>= 1) m = fmaxf(m, __shfl_xor_sync(0xffffffffu, m, o));
    if ((tid & 31) == 0) red[tid >> 5] = m;
    __syncthreads();
    if (tid == 0) {
        float t = red[0];
        #pragma unroll
        for (int i = 1; i < 8; i++) t = fmaxf(t, red[i]);
        red[8] = t;
    }
    __syncthreads();
    float ex = expf(v - red[8]);
    float s = ex;
    #pragma unroll
    for (int o = 16; o; o >>= 1) s += __shfl_xor_sync(0xffffffffu, s, o);
    if ((tid & 31) == 0) red[tid >> 5] = s;
    __syncthreads();
    if (tid == 0) {
        float t = 0.f;
        #pragma unroll
        for (int i = 0; i < 8; i++) t += red[i];
        red[9] = t;
    }
    __syncthreads();
    float prob = ex / red[9];

    g_sel_idx[e * CAP + tid]  = s_idx[tid];
    g_sel_prob[e * CAP + tid] = prob;
    atomicAdd(&g_counts[s_idx[tid]], 1);
}

// ---------------- output fill (zeros + capacity tail) + counts reset ----------------
__global__ void fill_kernel(float* __restrict__ out, long long out_size) {
    long long g = (long long)blockIdx.x * blockDim.x + threadIdx.x;
    long long stride = (long long)gridDim.x * blockDim.x;
    const long long NE2 = 2LL * NTOK * NEXP;

    float4 z4 = make_float4(0.f, 0.f, 0.f, 0.f);
    float4* o4 = (float4*)out;
    long long n4 = NE2 >> 2;
    long long lim4 = (out_size >> 2) < n4 ? (out_size >> 2) : n4;
    for (long long i = g; i < lim4; i += stride) o4[i] = z4;
    for (long long i = NE2 + g; i < out_size; i += stride) out[i] = (float)CAP;

    for (long long i = g; i < NTOK; i += stride) g_counts[i] = 0;
}

// ---------------- scatter: weights = prob/count, assignments = 1 ----------------
__global__ void scatter_kernel(float* __restrict__ out) {
    int idx = blockIdx.x * blockDim.x + threadIdx.x;   // 0 .. E*CAP-1
    int e = idx >> 8;
    int n = g_sel_idx[idx];
    float p = g_sel_prob[idx];
    int c = g_counts[n];
    out[(size_t)n * NEXP + e] = p / (float)c;
    out[(size_t)NTOK * NEXP + (size_t)n * NEXP + e] = 1.0f;
}

// ---------------- launch ----------------
extern "C" void kernel_launch(void* const* d_in, const int* in_sizes, int n_in,
                              void* d_out, int out_size) {
    (void)in_sizes; (void)n_in;
    const float* hs = (const float*)d_in[0];   // hidden_states [4,4096,2048] fp32
    const float* ws = (const float*)d_in[1];   // w_sel [64,2048] fp32
    float* out = (float*)d_out;

    fill_kernel<<<2048, 256>>>(out, (long long)out_size);
    gemm_imma_kernel<<<NTOK / BT, 512>>>(hs, ws);
    topk_kernel<<<NEXP, 256>>>();
    scatter_kernel<<<NEXP * CAP / 256, 256>>>(out);
}